// round 1
// baseline (speedup 1.0000x reference)
#include <cuda_runtime.h>

// Problem constants (B=2, H=16, S=2048, D=64, causal)
#define BH     32
#define SEQ    2048
#define DH     64
#define BM     128          // query rows per CTA
#define BN     64           // key cols per kv-tile
#define PAD    68           // floats per smem row (16B-aligned, conflict-free LDS.128)
#define NTHR   256

// smem partition offsets (in floats)
#define OFF_Q  0
#define OFF_K  (BM * PAD)                 // 128*68
#define OFF_VT (OFF_K + BN * PAD)         // +64*68
#define OFF_P  (OFF_VT + BN * PAD)        // +64*68
#define SMEM_FLOATS (OFF_P + BM * PAD)    // 384*68 = 26112 floats = 104448 B

__global__ __launch_bounds__(NTHR)
void fattn_fp32_kernel(const float* __restrict__ Qg,
                       const float* __restrict__ Kg,
                       const float* __restrict__ Vg,
                       float* __restrict__ Og)
{
    extern __shared__ float sm[];
    float* Qs = sm + OFF_Q;   // [BM][PAD]  row-major over k
    float* Ks = sm + OFF_K;   // [BN][PAD]  Ks[c][k]
    float* Vt = sm + OFF_VT;  // [BN][PAD]  Vt[c][k]  (transposed V)
    float* Ps = sm + OFF_P;   // [BM][PAD]  Ps[r][k]

    const int qt  = blockIdx.x;        // 0..15
    const int bh  = blockIdx.y;        // 0..31
    const int tid = threadIdx.x;       // 0..255
    const int ty  = tid >> 4;          // 0..15  -> rows ty*8 .. ty*8+7
    const int tx  = tid & 15;          // 0..15  -> cols tx, tx+16, tx+32, tx+48

    const size_t base = (size_t)bh * SEQ * DH;
    const float* Qb = Qg + base + (size_t)qt * BM * DH;

    // ---- load Q tile (128x64) : gmem float4 -> smem scalars (k-major, padded)
    #pragma unroll
    for (int it = 0; it < (BM * DH / 4) / NTHR; it++) {
        int i = tid + it * NTHR;
        int r = i >> 4;                 // 16 float4 per row
        int c = (i & 15) << 2;
        float4 v = *(const float4*)(Qb + r * DH + c);
        float* dst = &Qs[r * PAD + c];
        dst[0] = v.x; dst[1] = v.y; dst[2] = v.z; dst[3] = v.w;
    }

    float o[8][4];
    float mrow[8], lrow[8];
    #pragma unroll
    for (int i = 0; i < 8; i++) {
        mrow[i] = -1e30f; lrow[i] = 0.f;
        #pragma unroll
        for (int m = 0; m < 4; m++) o[i][m] = 0.f;
    }

    const int n_kv = 2 * qt + 2;       // causal: kv tiles 0 .. 2qt+1

    for (int kt = 0; kt < n_kv; kt++) {
        const float* Kb = Kg + base + (size_t)kt * BN * DH;
        const float* Vb = Vg + base + (size_t)kt * BN * DH;

        __syncthreads();   // prev GEMM2 done (and Q tile visible on iter 0)

        // ---- load K tile (64x64), direct copy (gmem already [key][d] = [c][k])
        #pragma unroll
        for (int it = 0; it < (BN * DH / 4) / NTHR; it++) {
            int i = tid + it * NTHR;
            int r = i >> 4;
            int c = (i & 15) << 2;
            float4 v = *(const float4*)(Kb + r * DH + c);
            float* dst = &Ks[r * PAD + c];
            dst[0] = v.x; dst[1] = v.y; dst[2] = v.z; dst[3] = v.w;
        }
        // ---- load V tile transposed: gmem V[k][c] -> Vt[c][k]
        #pragma unroll
        for (int it = 0; it < (BN * DH / 4) / NTHR; it++) {
            int i = tid + it * NTHR;
            int k = i >> 4;
            int c = (i & 15) << 2;
            float4 v = *(const float4*)(Vb + k * DH + c);
            Vt[(c + 0) * PAD + k] = v.x;
            Vt[(c + 1) * PAD + k] = v.y;
            Vt[(c + 2) * PAD + k] = v.z;
            Vt[(c + 3) * PAD + k] = v.w;
        }
        __syncthreads();

        // ---- GEMM1: s[8][4] = Q(8 rows) . K^T(4 cols), k-vectorized
        float s[8][4];
        #pragma unroll
        for (int i = 0; i < 8; i++)
            #pragma unroll
            for (int m = 0; m < 4; m++) s[i][m] = 0.f;

        #pragma unroll 2
        for (int kk = 0; kk < DH; kk += 4) {
            float4 kf0 = *(const float4*)&Ks[(tx     ) * PAD + kk];
            float4 kf1 = *(const float4*)&Ks[(tx + 16) * PAD + kk];
            float4 kf2 = *(const float4*)&Ks[(tx + 32) * PAD + kk];
            float4 kf3 = *(const float4*)&Ks[(tx + 48) * PAD + kk];
            #pragma unroll
            for (int i = 0; i < 8; i++) {
                float4 qf = *(const float4*)&Qs[(ty * 8 + i) * PAD + kk];
                s[i][0] = fmaf(qf.x, kf0.x, fmaf(qf.y, kf0.y, fmaf(qf.z, kf0.z, fmaf(qf.w, kf0.w, s[i][0]))));
                s[i][1] = fmaf(qf.x, kf1.x, fmaf(qf.y, kf1.y, fmaf(qf.z, kf1.z, fmaf(qf.w, kf1.w, s[i][1]))));
                s[i][2] = fmaf(qf.x, kf2.x, fmaf(qf.y, kf2.y, fmaf(qf.z, kf2.z, fmaf(qf.w, kf2.w, s[i][2]))));
                s[i][3] = fmaf(qf.x, kf3.x, fmaf(qf.y, kf3.y, fmaf(qf.z, kf3.z, fmaf(qf.w, kf3.w, s[i][3]))));
            }
        }

        // ---- scale + causal mask (only near diagonal)
        const float scale = 0.125f;  // 1/sqrt(64)
        const bool diag = (kt * BN + BN - 1) > (qt * BM);
        #pragma unroll
        for (int i = 0; i < 8; i++) {
            int qglob = qt * BM + ty * 8 + i;
            #pragma unroll
            for (int m = 0; m < 4; m++) {
                float v = s[i][m] * scale;
                if (diag) {
                    int kglob = kt * BN + tx + 16 * m;
                    if (kglob > qglob) v = -1e30f;
                }
                s[i][m] = v;
            }
        }

        // ---- online softmax (row reductions over the 16-lane half-warp)
        #pragma unroll
        for (int i = 0; i < 8; i++) {
            float mx = fmaxf(fmaxf(s[i][0], s[i][1]), fmaxf(s[i][2], s[i][3]));
            mx = fmaxf(mx, __shfl_xor_sync(0xffffffffu, mx, 8));
            mx = fmaxf(mx, __shfl_xor_sync(0xffffffffu, mx, 4));
            mx = fmaxf(mx, __shfl_xor_sync(0xffffffffu, mx, 2));
            mx = fmaxf(mx, __shfl_xor_sync(0xffffffffu, mx, 1));
            float mn = fmaxf(mrow[i], mx);

            float p0 = __expf(s[i][0] - mn);
            float p1 = __expf(s[i][1] - mn);
            float p2 = __expf(s[i][2] - mn);
            float p3 = __expf(s[i][3] - mn);
            float rs = (p0 + p1) + (p2 + p3);
            rs += __shfl_xor_sync(0xffffffffu, rs, 8);
            rs += __shfl_xor_sync(0xffffffffu, rs, 4);
            rs += __shfl_xor_sync(0xffffffffu, rs, 2);
            rs += __shfl_xor_sync(0xffffffffu, rs, 1);

            float alpha = __expf(mrow[i] - mn);
            lrow[i] = lrow[i] * alpha + rs;
            mrow[i] = mn;
            #pragma unroll
            for (int m = 0; m < 4; m++) o[i][m] *= alpha;

            float* pr = &Ps[(ty * 8 + i) * PAD + tx];
            pr[ 0] = p0;
            pr[16] = p1;
            pr[32] = p2;
            pr[48] = p3;
        }
        __syncthreads();

        // ---- GEMM2: o[8][4] += P(8 rows) . V(4 cols), k-vectorized
        #pragma unroll 2
        for (int kk = 0; kk < BN; kk += 4) {
            float4 vf0 = *(const float4*)&Vt[(tx     ) * PAD + kk];
            float4 vf1 = *(const float4*)&Vt[(tx + 16) * PAD + kk];
            float4 vf2 = *(const float4*)&Vt[(tx + 32) * PAD + kk];
            float4 vf3 = *(const float4*)&Vt[(tx + 48) * PAD + kk];
            #pragma unroll
            for (int i = 0; i < 8; i++) {
                float4 pf = *(const float4*)&Ps[(ty * 8 + i) * PAD + kk];
                o[i][0] = fmaf(pf.x, vf0.x, fmaf(pf.y, vf0.y, fmaf(pf.z, vf0.z, fmaf(pf.w, vf0.w, o[i][0]))));
                o[i][1] = fmaf(pf.x, vf1.x, fmaf(pf.y, vf1.y, fmaf(pf.z, vf1.z, fmaf(pf.w, vf1.w, o[i][1]))));
                o[i][2] = fmaf(pf.x, vf2.x, fmaf(pf.y, vf2.y, fmaf(pf.z, vf2.z, fmaf(pf.w, vf2.w, o[i][2]))));
                o[i][3] = fmaf(pf.x, vf3.x, fmaf(pf.y, vf3.y, fmaf(pf.z, vf3.z, fmaf(pf.w, vf3.w, o[i][3]))));
            }
        }
    }

    // ---- epilogue: normalize and store
    float* Ob = Og + base + (size_t)qt * BM * DH;
    #pragma unroll
    for (int i = 0; i < 8; i++) {
        float inv = 1.0f / lrow[i];
        float* orow = Ob + (ty * 8 + i) * DH + tx;
        orow[ 0] = o[i][0] * inv;
        orow[16] = o[i][1] * inv;
        orow[32] = o[i][2] * inv;
        orow[48] = o[i][3] * inv;
    }
}

extern "C" void kernel_launch(void* const* d_in, const int* in_sizes, int n_in,
                              void* d_out, int out_size)
{
    const float* Q = (const float*)d_in[0];
    const float* K = (const float*)d_in[1];
    const float* V = (const float*)d_in[2];
    // d_in[3] = causal_mask (bool tril) — pattern is computed analytically.
    float* O = (float*)d_out;

    const int smem_bytes = SMEM_FLOATS * sizeof(float);  // 104448
    cudaFuncSetAttribute(fattn_fp32_kernel,
                         cudaFuncAttributeMaxDynamicSharedMemorySize, smem_bytes);

    dim3 grid(SEQ / BM, BH);   // (16, 32)
    fattn_fp32_kernel<<<grid, NTHR, smem_bytes>>>(Q, K, V, O);
}

// round 3
// speedup vs baseline: 3.2296x; 3.2296x over previous
#include <cuda_runtime.h>
#include <cstdint>

// B=2,H=16,S=2048,D=64 causal attention, fp32 in/out.
#define BHN   32
#define SEQ   2048
#define DH    64
#define BM    128
#define BN    64
#define NTHR  256

#define LDB   144                 // bytes per smem row (64 bf16 + 8 pad)
#define SM_KHI 0
#define SM_KLO 9216
#define SM_VHI 18432
#define SM_VLO 27648
#define SM_QLO 18432              // Q staging overlays K/V region (used before loop)
#define SMEM_BYTES 36864

__device__ __forceinline__ uint32_t smem_u32(const void* p) {
    uint32_t a;
    asm("{ .reg .u64 t; cvta.to.shared.u64 t, %1; cvt.u32.u64 %0, t; }" : "=r"(a) : "l"(p));
    return a;
}
__device__ __forceinline__ void ldsm4(uint32_t r[4], uint32_t addr) {
    asm volatile("ldmatrix.sync.aligned.m8n8.x4.shared.b16 {%0,%1,%2,%3}, [%4];"
        : "=r"(r[0]), "=r"(r[1]), "=r"(r[2]), "=r"(r[3]) : "r"(addr));
}
__device__ __forceinline__ void ldsm4t(uint32_t r[4], uint32_t addr) {
    asm volatile("ldmatrix.sync.aligned.m8n8.x4.trans.shared.b16 {%0,%1,%2,%3}, [%4];"
        : "=r"(r[0]), "=r"(r[1]), "=r"(r[2]), "=r"(r[3]) : "r"(addr));
}
__device__ __forceinline__ void mma_bf16(float c[4], const uint32_t a[4],
                                         uint32_t b0, uint32_t b1) {
    asm volatile("mma.sync.aligned.m16n8k16.row.col.f32.bf16.bf16.f32 "
        "{%0,%1,%2,%3}, {%4,%5,%6,%7}, {%8,%9}, {%0,%1,%2,%3};"
        : "+f"(c[0]), "+f"(c[1]), "+f"(c[2]), "+f"(c[3])
        : "r"(a[0]), "r"(a[1]), "r"(a[2]), "r"(a[3]), "r"(b0), "r"(b1));
}
// pack two floats into bf16x2 (lo -> low half / smaller col index)
__device__ __forceinline__ uint32_t packbf(float lo, float hi) {
    uint32_t r;
    asm("cvt.rn.bf16x2.f32 %0, %1, %2;" : "=r"(r) : "f"(hi), "f"(lo));
    return r;
}
// split (x,y) into bf16x2 hi part and bf16x2 residual part
__device__ __forceinline__ void split2(float x, float y, uint32_t& h, uint32_t& l) {
    h = packbf(x, y);
    float hx = __uint_as_float(h << 16);
    float hy = __uint_as_float(h & 0xffff0000u);
    l = packbf(x - hx, y - hy);
}

__global__ __launch_bounds__(NTHR)
void fattn_mma_kernel(const float* __restrict__ Qg,
                      const float* __restrict__ Kg,
                      const float* __restrict__ Vg,
                      float* __restrict__ Og)
{
    __shared__ __align__(1024) uint8_t smem[SMEM_BYTES];
    const uint32_t sb = smem_u32(smem);

    const int tid  = threadIdx.x;
    const int w    = tid >> 5;
    const int lane = tid & 31;
    const int lr   = lane & 15;          // ldmatrix row select
    const int lc   = (lane >> 4) << 3;   // ldmatrix col select (0 or 8)
    const int quad = lane & 3;

    const int qt = (gridDim.x - 1) - blockIdx.x;   // heavy tiles first
    const int bh = blockIdx.y;
    const size_t base = (size_t)bh * SEQ * DH;
    const float* Qb = Qg + base + (size_t)qt * BM * DH;

    // ---- stage Q (scaled by 1/8), split hi/lo into smem ----
    #pragma unroll
    for (int it = 0; it < 8; it++) {
        int i  = tid + it * NTHR;        // 0..2047 float4
        int r  = i >> 4;
        int c4 = (i & 15) << 2;
        float4 v = *(const float4*)(Qb + r * DH + c4);
        v.x *= 0.125f; v.y *= 0.125f; v.z *= 0.125f; v.w *= 0.125f;
        uint2 h, l;
        split2(v.x, v.y, h.x, l.x);
        split2(v.z, v.w, h.y, l.y);
        uint32_t off = (uint32_t)(r * LDB + c4 * 2);
        *(uint2*)(smem + off)          = h;
        *(uint2*)(smem + SM_QLO + off) = l;
    }
    __syncthreads();

    // ---- persistent Q fragments (4 k-steps x 4 regs, hi & lo) ----
    uint32_t qh[4][4], ql[4][4];
    #pragma unroll
    for (int ks = 0; ks < 4; ks++) {
        uint32_t a = sb + (uint32_t)((w * 16 + lr) * LDB + (ks * 16 + lc) * 2);
        ldsm4(qh[ks], a);
        ldsm4(ql[ks], a + SM_QLO);
    }
    __syncthreads();   // Q staging area now reusable for K/V

    float o[8][4];
    #pragma unroll
    for (int n = 0; n < 8; n++)
        #pragma unroll
        for (int j = 0; j < 4; j++) o[n][j] = 0.f;
    float m0 = -1e30f, m1 = -1e30f, l0 = 0.f, l1 = 0.f;

    const int rowloc0 = w * 16 + (lane >> 2);
    const int qg0 = qt * BM + rowloc0;        // global q row for c0/c1
    const int n_kv = 2 * qt + 2;

    for (int kt = 0; kt < n_kv; kt++) {
        const float* Kb = Kg + base + (size_t)kt * BN * DH;
        const float* Vb = Vg + base + (size_t)kt * BN * DH;

        __syncthreads();   // prior iteration's ldmatrix reads complete

        // ---- load + convert K,V tiles (64x64 each) ----
        #pragma unroll
        for (int it = 0; it < 4; it++) {
            int i  = tid + it * NTHR;     // 0..1023 float4
            int r  = i >> 4;
            int c4 = (i & 15) << 2;
            uint32_t off = (uint32_t)(r * LDB + c4 * 2);
            float4 kv = *(const float4*)(Kb + r * DH + c4);
            uint2 h, l;
            split2(kv.x, kv.y, h.x, l.x);
            split2(kv.z, kv.w, h.y, l.y);
            *(uint2*)(smem + SM_KHI + off) = h;
            *(uint2*)(smem + SM_KLO + off) = l;
            float4 vv = *(const float4*)(Vb + r * DH + c4);
            split2(vv.x, vv.y, h.x, l.x);
            split2(vv.z, vv.w, h.y, l.y);
            *(uint2*)(smem + SM_VHI + off) = h;
            *(uint2*)(smem + SM_VLO + off) = l;
        }
        __syncthreads();

        // ---- S = Qhi.Khi + Qlo.Khi + Qhi.Klo ----
        float s[8][4];
        #pragma unroll
        for (int n = 0; n < 8; n++)
            #pragma unroll
            for (int j = 0; j < 4; j++) s[n][j] = 0.f;

        #pragma unroll
        for (int ks = 0; ks < 4; ks++) {
            #pragma unroll
            for (int kg = 0; kg < 4; kg++) {
                uint32_t addr = sb + (uint32_t)((kg * 16 + lr) * LDB + (ks * 16 + lc) * 2);
                uint32_t bhf[4], blf[4];
                ldsm4(bhf, addr + SM_KHI);
                mma_bf16(s[2*kg],   qh[ks], bhf[0], bhf[2]);
                mma_bf16(s[2*kg+1], qh[ks], bhf[1], bhf[3]);
                mma_bf16(s[2*kg],   ql[ks], bhf[0], bhf[2]);
                mma_bf16(s[2*kg+1], ql[ks], bhf[1], bhf[3]);
                ldsm4(blf, addr + SM_KLO);
                mma_bf16(s[2*kg],   qh[ks], blf[0], blf[2]);
                mma_bf16(s[2*kg+1], qh[ks], blf[1], blf[3]);
            }
        }

        // ---- causal mask (diagonal tiles only) ----
        if (kt >= 2 * qt) {
            #pragma unroll
            for (int n = 0; n < 8; n++) {
                int kb = kt * BN + n * 8 + quad * 2;
                if (kb     > qg0)     s[n][0] = -1e30f;
                if (kb + 1 > qg0)     s[n][1] = -1e30f;
                if (kb     > qg0 + 8) s[n][2] = -1e30f;
                if (kb + 1 > qg0 + 8) s[n][3] = -1e30f;
            }
        }

        // ---- online softmax (rows live in quads) ----
        float mx0 = s[0][0], mx1 = s[0][2];
        #pragma unroll
        for (int n = 0; n < 8; n++) {
            mx0 = fmaxf(mx0, fmaxf(s[n][0], s[n][1]));
            mx1 = fmaxf(mx1, fmaxf(s[n][2], s[n][3]));
        }
        mx0 = fmaxf(mx0, __shfl_xor_sync(0xffffffffu, mx0, 1));
        mx0 = fmaxf(mx0, __shfl_xor_sync(0xffffffffu, mx0, 2));
        mx1 = fmaxf(mx1, __shfl_xor_sync(0xffffffffu, mx1, 1));
        mx1 = fmaxf(mx1, __shfl_xor_sync(0xffffffffu, mx1, 2));

        float mn0 = fmaxf(m0, mx0), mn1 = fmaxf(m1, mx1);
        float a0 = __expf(m0 - mn0), a1 = __expf(m1 - mn1);
        m0 = mn0; m1 = mn1;

        float rs0 = 0.f, rs1 = 0.f;
        #pragma unroll
        for (int n = 0; n < 8; n++) {
            s[n][0] = __expf(s[n][0] - m0); rs0 += s[n][0];
            s[n][1] = __expf(s[n][1] - m0); rs0 += s[n][1];
            s[n][2] = __expf(s[n][2] - m1); rs1 += s[n][2];
            s[n][3] = __expf(s[n][3] - m1); rs1 += s[n][3];
        }
        rs0 += __shfl_xor_sync(0xffffffffu, rs0, 1);
        rs0 += __shfl_xor_sync(0xffffffffu, rs0, 2);
        rs1 += __shfl_xor_sync(0xffffffffu, rs1, 1);
        rs1 += __shfl_xor_sync(0xffffffffu, rs1, 2);
        l0 = l0 * a0 + rs0;
        l1 = l1 * a1 + rs1;

        #pragma unroll
        for (int n = 0; n < 8; n++) {
            o[n][0] *= a0; o[n][1] *= a0;
            o[n][2] *= a1; o[n][3] *= a1;
        }

        // ---- P -> A-fragments (hi + residual), register-only ----
        uint32_t pa[4][4], pl[4][4];
        #pragma unroll
        for (int j = 0; j < 4; j++) {
            split2(s[2*j][0],   s[2*j][1],   pa[j][0], pl[j][0]);
            split2(s[2*j][2],   s[2*j][3],   pa[j][1], pl[j][1]);
            split2(s[2*j+1][0], s[2*j+1][1], pa[j][2], pl[j][2]);
            split2(s[2*j+1][2], s[2*j+1][3], pa[j][3], pl[j][3]);
        }

        // ---- O += Phi.Vhi + Plo.Vhi + Phi.Vlo ----
        #pragma unroll
        for (int ks = 0; ks < 4; ks++) {
            #pragma unroll
            for (int dg = 0; dg < 4; dg++) {
                uint32_t addr = sb + (uint32_t)((ks * 16 + lr) * LDB + (dg * 16 + lc) * 2);
                uint32_t vhf[4], vlf[4];
                ldsm4t(vhf, addr + SM_VHI);
                mma_bf16(o[2*dg],   pa[ks], vhf[0], vhf[1]);
                mma_bf16(o[2*dg+1], pa[ks], vhf[2], vhf[3]);
                mma_bf16(o[2*dg],   pl[ks], vhf[0], vhf[1]);
                mma_bf16(o[2*dg+1], pl[ks], vhf[2], vhf[3]);
                ldsm4t(vlf, addr + SM_VLO);
                mma_bf16(o[2*dg],   pa[ks], vlf[0], vlf[1]);
                mma_bf16(o[2*dg+1], pa[ks], vlf[2], vlf[3]);
            }
        }
    }

    // ---- epilogue ----
    float inv0 = 1.0f / l0, inv1 = 1.0f / l1;
    float* Orow0 = Og + base + (size_t)qg0 * DH;
    float* Orow1 = Orow0 + 8 * DH;
    #pragma unroll
    for (int n = 0; n < 8; n++) {
        int d = n * 8 + quad * 2;
        *(float2*)(Orow0 + d) = make_float2(o[n][0] * inv0, o[n][1] * inv0);
        *(float2*)(Orow1 + d) = make_float2(o[n][2] * inv1, o[n][3] * inv1);
    }
}

extern "C" void kernel_launch(void* const* d_in, const int* in_sizes, int n_in,
                              void* d_out, int out_size)
{
    const float* Q = (const float*)d_in[0];
    const float* K = (const float*)d_in[1];
    const float* V = (const float*)d_in[2];
    float* O = (float*)d_out;

    dim3 grid(SEQ / BM, BHN);   // (16, 32)
    fattn_mma_kernel<<<grid, NTHR>>>(Q, K, V, O);
}

// round 4
// speedup vs baseline: 3.5025x; 1.0845x over previous
#include <cuda_runtime.h>
#include <cstdint>

// B=2,H=16,S=2048,D=64 causal attention, fp32 in/out.
#define BHN   32
#define SEQ   2048
#define DH    64
#define BM    128
#define BN    64
#define NTHR  256

#define LDB    144                // bytes per smem row (64 bf16 + 8 pad)
#define SM_KHI 0
#define SM_KLO 9216
#define SM_VHI 18432
#define SM_VLO 27648
#define BUF    36864              // one K/V tile-set buffer
#define SM_QHI BUF                // Q staging overlays buffer 1 (pre-loop only)
#define SM_QLO (BUF + 18432)
#define SMEM_BYTES (2 * BUF)      // 73728

__device__ __forceinline__ uint32_t smem_u32(const void* p) {
    uint32_t a;
    asm("{ .reg .u64 t; cvta.to.shared.u64 t, %1; cvt.u32.u64 %0, t; }" : "=r"(a) : "l"(p));
    return a;
}
__device__ __forceinline__ void ldsm4(uint32_t r[4], uint32_t addr) {
    asm volatile("ldmatrix.sync.aligned.m8n8.x4.shared.b16 {%0,%1,%2,%3}, [%4];"
        : "=r"(r[0]), "=r"(r[1]), "=r"(r[2]), "=r"(r[3]) : "r"(addr));
}
__device__ __forceinline__ void ldsm4t(uint32_t r[4], uint32_t addr) {
    asm volatile("ldmatrix.sync.aligned.m8n8.x4.trans.shared.b16 {%0,%1,%2,%3}, [%4];"
        : "=r"(r[0]), "=r"(r[1]), "=r"(r[2]), "=r"(r[3]) : "r"(addr));
}
__device__ __forceinline__ void mma_bf16(float c[4], const uint32_t a[4],
                                         uint32_t b0, uint32_t b1) {
    asm volatile("mma.sync.aligned.m16n8k16.row.col.f32.bf16.bf16.f32 "
        "{%0,%1,%2,%3}, {%4,%5,%6,%7}, {%8,%9}, {%0,%1,%2,%3};"
        : "+f"(c[0]), "+f"(c[1]), "+f"(c[2]), "+f"(c[3])
        : "r"(a[0]), "r"(a[1]), "r"(a[2]), "r"(a[3]), "r"(b0), "r"(b1));
}
__device__ __forceinline__ uint32_t packbf(float lo, float hi) {
    uint32_t r;
    asm("cvt.rn.bf16x2.f32 %0, %1, %2;" : "=r"(r) : "f"(hi), "f"(lo));
    return r;
}
__device__ __forceinline__ void split2(float x, float y, uint32_t& h, uint32_t& l) {
    h = packbf(x, y);
    float hx = __uint_as_float(h << 16);
    float hy = __uint_as_float(h & 0xffff0000u);
    l = packbf(x - hx, y - hy);
}

__global__ __launch_bounds__(NTHR, 1)
void fattn_mma_kernel(const float* __restrict__ Qg,
                      const float* __restrict__ Kg,
                      const float* __restrict__ Vg,
                      float* __restrict__ Og)
{
    extern __shared__ __align__(1024) uint8_t smem[];
    const uint32_t sb = smem_u32(smem);

    const int tid  = threadIdx.x;
    const int w    = tid >> 5;
    const int lane = tid & 31;
    const int lr   = lane & 15;
    const int lc   = (lane >> 4) << 3;
    const int quad = lane & 3;

    const int qt = (gridDim.x - 1) - blockIdx.x;   // heavy tiles first
    const int bh = blockIdx.y;
    const size_t base = (size_t)bh * SEQ * DH;
    const float* Qb = Qg + base + (size_t)qt * BM * DH;

    // ---- stage Q (scaled), split hi/lo into smem buffer-1 area ----
    #pragma unroll
    for (int it = 0; it < 8; it++) {
        int i  = tid + it * NTHR;
        int r  = i >> 4;
        int c4 = (i & 15) << 2;
        float4 v = *(const float4*)(Qb + r * DH + c4);
        v.x *= 0.125f; v.y *= 0.125f; v.z *= 0.125f; v.w *= 0.125f;
        uint2 h, l;
        split2(v.x, v.y, h.x, l.x);
        split2(v.z, v.w, h.y, l.y);
        uint32_t off = (uint32_t)(r * LDB + c4 * 2);
        *(uint2*)(smem + SM_QHI + off) = h;
        *(uint2*)(smem + SM_QLO + off) = l;
    }
    __syncthreads();

    // ---- persistent Q fragments ----
    uint32_t qh[4][4], ql[4][4];
    #pragma unroll
    for (int ks = 0; ks < 4; ks++) {
        uint32_t a = sb + (uint32_t)((w * 16 + lr) * LDB + (ks * 16 + lc) * 2);
        ldsm4(qh[ks], a + SM_QHI);
        ldsm4(ql[ks], a + SM_QLO);
    }
    __syncthreads();   // Q staging area (buffer 1) now reusable

    float o[8][4];
    #pragma unroll
    for (int n = 0; n < 8; n++)
        #pragma unroll
        for (int j = 0; j < 4; j++) o[n][j] = 0.f;
    float m0 = -1e30f, m1 = -1e30f, l0 = 0.f, l1 = 0.f;

    const int rowloc0 = w * 16 + (lane >> 2);
    const int qg0 = qt * BM + rowloc0;
    const int n_kv = 2 * qt + 2;

    // per-thread gmem/smem load indices (same every tile)
    const int li_r  = tid >> 4;          // used with it stride: r = li_r + it*16
    const int li_c4 = (tid & 15) << 2;

    // ---- prologue: load tile 0 into regs, convert, store to buffer 0 ----
    float4 kreg[4], vreg[4];
    {
        const float* Kb = Kg + base;
        const float* Vb = Vg + base;
        #pragma unroll
        for (int it = 0; it < 4; it++) {
            int r = li_r + it * 16;
            kreg[it] = *(const float4*)(Kb + r * DH + li_c4);
            vreg[it] = *(const float4*)(Vb + r * DH + li_c4);
        }
        #pragma unroll
        for (int it = 0; it < 4; it++) {
            int r = li_r + it * 16;
            uint32_t off = (uint32_t)(r * LDB + li_c4 * 2);
            uint2 h, l;
            split2(kreg[it].x, kreg[it].y, h.x, l.x);
            split2(kreg[it].z, kreg[it].w, h.y, l.y);
            *(uint2*)(smem + SM_KHI + off) = h;
            *(uint2*)(smem + SM_KLO + off) = l;
            split2(vreg[it].x, vreg[it].y, h.x, l.x);
            split2(vreg[it].z, vreg[it].w, h.y, l.y);
            *(uint2*)(smem + SM_VHI + off) = h;
            *(uint2*)(smem + SM_VLO + off) = l;
        }
    }
    __syncthreads();

    for (int kt = 0; kt < n_kv; kt++) {
        const uint32_t cur = (uint32_t)(kt & 1) * BUF;
        const uint32_t nxt = cur ^ BUF;
        const bool have_next = (kt + 1 < n_kv);

        // ---- prefetch next tile's K/V into registers (latency hides under MMAs) ----
        if (have_next) {
            const float* Kb = Kg + base + (size_t)(kt + 1) * BN * DH;
            const float* Vb = Vg + base + (size_t)(kt + 1) * BN * DH;
            #pragma unroll
            for (int it = 0; it < 4; it++) {
                int r = li_r + it * 16;
                kreg[it] = *(const float4*)(Kb + r * DH + li_c4);
                vreg[it] = *(const float4*)(Vb + r * DH + li_c4);
            }
        }

        // ---- S = Qhi.Khi + Qlo.Khi + Qhi.Klo ----
        float s[8][4];
        #pragma unroll
        for (int n = 0; n < 8; n++)
            #pragma unroll
            for (int j = 0; j < 4; j++) s[n][j] = 0.f;

        #pragma unroll
        for (int ks = 0; ks < 4; ks++) {
            #pragma unroll
            for (int kg = 0; kg < 4; kg++) {
                uint32_t addr = sb + cur + (uint32_t)((kg * 16 + lr) * LDB + (ks * 16 + lc) * 2);
                uint32_t bhf[4], blf[4];
                ldsm4(bhf, addr + SM_KHI);
                mma_bf16(s[2*kg],   qh[ks], bhf[0], bhf[2]);
                mma_bf16(s[2*kg+1], qh[ks], bhf[1], bhf[3]);
                mma_bf16(s[2*kg],   ql[ks], bhf[0], bhf[2]);
                mma_bf16(s[2*kg+1], ql[ks], bhf[1], bhf[3]);
                ldsm4(blf, addr + SM_KLO);
                mma_bf16(s[2*kg],   qh[ks], blf[0], blf[2]);
                mma_bf16(s[2*kg+1], qh[ks], blf[1], blf[3]);
            }
        }

        // ---- causal mask (diagonal tiles only) ----
        if (kt >= 2 * qt) {
            #pragma unroll
            for (int n = 0; n < 8; n++) {
                int kb = kt * BN + n * 8 + quad * 2;
                if (kb     > qg0)     s[n][0] = -1e30f;
                if (kb + 1 > qg0)     s[n][1] = -1e30f;
                if (kb     > qg0 + 8) s[n][2] = -1e30f;
                if (kb + 1 > qg0 + 8) s[n][3] = -1e30f;
            }
        }

        // ---- online softmax ----
        float mx0 = s[0][0], mx1 = s[0][2];
        #pragma unroll
        for (int n = 0; n < 8; n++) {
            mx0 = fmaxf(mx0, fmaxf(s[n][0], s[n][1]));
            mx1 = fmaxf(mx1, fmaxf(s[n][2], s[n][3]));
        }
        mx0 = fmaxf(mx0, __shfl_xor_sync(0xffffffffu, mx0, 1));
        mx0 = fmaxf(mx0, __shfl_xor_sync(0xffffffffu, mx0, 2));
        mx1 = fmaxf(mx1, __shfl_xor_sync(0xffffffffu, mx1, 1));
        mx1 = fmaxf(mx1, __shfl_xor_sync(0xffffffffu, mx1, 2));

        float mn0 = fmaxf(m0, mx0), mn1 = fmaxf(m1, mx1);
        float a0 = __expf(m0 - mn0), a1 = __expf(m1 - mn1);
        m0 = mn0; m1 = mn1;

        float rs0 = 0.f, rs1 = 0.f;
        #pragma unroll
        for (int n = 0; n < 8; n++) {
            s[n][0] = __expf(s[n][0] - m0); rs0 += s[n][0];
            s[n][1] = __expf(s[n][1] - m0); rs0 += s[n][1];
            s[n][2] = __expf(s[n][2] - m1); rs1 += s[n][2];
            s[n][3] = __expf(s[n][3] - m1); rs1 += s[n][3];
        }
        rs0 += __shfl_xor_sync(0xffffffffu, rs0, 1);
        rs0 += __shfl_xor_sync(0xffffffffu, rs0, 2);
        rs1 += __shfl_xor_sync(0xffffffffu, rs1, 1);
        rs1 += __shfl_xor_sync(0xffffffffu, rs1, 2);
        l0 = l0 * a0 + rs0;
        l1 = l1 * a1 + rs1;

        #pragma unroll
        for (int n = 0; n < 8; n++) {
            o[n][0] *= a0; o[n][1] *= a0;
            o[n][2] *= a1; o[n][3] *= a1;
        }

        // ---- P -> A-fragments (hi + residual) ----
        uint32_t pa[4][4], pl[4][4];
        #pragma unroll
        for (int j = 0; j < 4; j++) {
            split2(s[2*j][0],   s[2*j][1],   pa[j][0], pl[j][0]);
            split2(s[2*j][2],   s[2*j][3],   pa[j][1], pl[j][1]);
            split2(s[2*j+1][0], s[2*j+1][1], pa[j][2], pl[j][2]);
            split2(s[2*j+1][2], s[2*j+1][3], pa[j][3], pl[j][3]);
        }

        // ---- convert + store next tile into the other buffer (overlaps PV GEMM) ----
        if (have_next) {
            #pragma unroll
            for (int it = 0; it < 4; it++) {
                int r = li_r + it * 16;
                uint32_t off = nxt + (uint32_t)(r * LDB + li_c4 * 2);
                uint2 h, l;
                split2(kreg[it].x, kreg[it].y, h.x, l.x);
                split2(kreg[it].z, kreg[it].w, h.y, l.y);
                *(uint2*)(smem + SM_KHI + off) = h;
                *(uint2*)(smem + SM_KLO + off) = l;
                split2(vreg[it].x, vreg[it].y, h.x, l.x);
                split2(vreg[it].z, vreg[it].w, h.y, l.y);
                *(uint2*)(smem + SM_VHI + off) = h;
                *(uint2*)(smem + SM_VLO + off) = l;
            }
        }

        // ---- O += Phi.Vhi + Plo.Vhi + Phi.Vlo ----
        #pragma unroll
        for (int ks = 0; ks < 4; ks++) {
            #pragma unroll
            for (int dg = 0; dg < 4; dg++) {
                uint32_t addr = sb + cur + (uint32_t)((ks * 16 + lr) * LDB + (dg * 16 + lc) * 2);
                uint32_t vhf[4], vlf[4];
                ldsm4t(vhf, addr + SM_VHI);
                mma_bf16(o[2*dg],   pa[ks], vhf[0], vhf[1]);
                mma_bf16(o[2*dg+1], pa[ks], vhf[2], vhf[3]);
                mma_bf16(o[2*dg],   pl[ks], vhf[0], vhf[1]);
                mma_bf16(o[2*dg+1], pl[ks], vhf[2], vhf[3]);
                ldsm4t(vlf, addr + SM_VLO);
                mma_bf16(o[2*dg],   pa[ks], vlf[0], vlf[1]);
                mma_bf16(o[2*dg+1], pa[ks], vlf[2], vlf[3]);
            }
        }

        __syncthreads();   // all warps done with `cur`; next tile's STS complete
    }

    // ---- epilogue ----
    float inv0 = 1.0f / l0, inv1 = 1.0f / l1;
    float* Orow0 = Og + base + (size_t)qg0 * DH;
    float* Orow1 = Orow0 + 8 * DH;
    #pragma unroll
    for (int n = 0; n < 8; n++) {
        int d = n * 8 + quad * 2;
        *(float2*)(Orow0 + d) = make_float2(o[n][0] * inv0, o[n][1] * inv0);
        *(float2*)(Orow1 + d) = make_float2(o[n][2] * inv1, o[n][3] * inv1);
    }
}

extern "C" void kernel_launch(void* const* d_in, const int* in_sizes, int n_in,
                              void* d_out, int out_size)
{
    const float* Q = (const float*)d_in[0];
    const float* K = (const float*)d_in[1];
    const float* V = (const float*)d_in[2];
    float* O = (float*)d_out;

    cudaFuncSetAttribute(fattn_mma_kernel,
                         cudaFuncAttributeMaxDynamicSharedMemorySize, SMEM_BYTES);
    dim3 grid(SEQ / BM, BHN);   // (16, 32)
    fattn_mma_kernel<<<grid, NTHR, SMEM_BYTES>>>(Q, K, V, O);
}